// round 3
// baseline (speedup 1.0000x reference)
#include <cuda_runtime.h>
#include <math.h>

#define NPIX  65536       // 256*256
#define SSAMP 128
#define EXW_  256
#define EXH_  128
#define NTEX  (EXH_*EXW_) // 32768 texels per batch image
#define PI_F  3.14159265358979f
#define RBLOCKS 512       // render grid (2 threads/pixel, 256 threads/block)

// Packed env: [0]=x b0, [1]=x b1, [2]=y b0, [3]=y b1 ; rgb + pad
__device__ float4 g_env4[4][NTEX];

// per-block partials + completion counter for fused reduction
__device__ double g_pl[RBLOCKS];
__device__ double g_ps[RBLOCKS];
__device__ unsigned int g_done;

__device__ __forceinline__ float clamp01(float x) {
    return fminf(fmaxf(x, 0.0f), 1.0f);
}

__global__ __launch_bounds__(256) void pack_kernel(
    const float* __restrict__ x, const float* __restrict__ y)
{
    int j   = blockIdx.x * 256 + threadIdx.x;   // 0..131071
    int arr = j >> 15;                          // 0..3
    int t   = j & (NTEX - 1);
    const float* src = (arr < 2 ? x : y) + ((size_t)(arr & 1) * NTEX + t) * 3;
    g_env4[arr][t] = make_float4(src[0], src[1], src[2], 0.0f);
}

__global__ __launch_bounds__(256) void render_kernel(
    const float* __restrict__ diffuse,// (3,256,256)
    const float* __restrict__ normal, // (3,256,256)
    const float* __restrict__ rough,  // (1,256,256)
    const float* __restrict__ seg,    // (256,256)
    const float* __restrict__ vmap,   // (3,256,256)
    const float* __restrict__ ls,     // (1,128,3)
    const float* __restrict__ ew,     // (1,128,1)
    const int*   __restrict__ idy,    // (128,256,256)
    const int*   __restrict__ idx,    // (128,256,256)
    float* __restrict__ out)          // [1 + 2*3*65536]
{
    __shared__ float s_ls[SSAMP * 3];
    __shared__ float s_ew[SSAMP];
    __shared__ double s_red[16];

    const int tid = threadIdx.x;
    for (int i = tid; i < SSAMP * 3; i += 256) s_ls[i] = ls[i];
    for (int i = tid; i < SSAMP;     i += 256) s_ew[i] = ew[i];
    __syncthreads();

    const int gt  = blockIdx.x * 256 + tid;
    const int pix = gt >> 1;       // 2 threads per pixel
    const int sub = gt & 1;        // sample half

    // ---- per-pixel constants ----
    const float nx = normal[pix], ny = normal[NPIX + pix], nz = normal[2 * NPIX + pix];
    const float vx = vmap[pix],   vy = vmap[NPIX + pix],   vz = vmap[2 * NPIX + pix];

    // camy = normalize(up - (up.n) n), up = (0,1,0)
    float cyx = -ny * nx;
    float cyy = 1.0f - ny * ny;
    float cyz = -ny * nz;
    {
        float cn  = sqrtf(cyx * cyx + cyy * cyy + cyz * cyz);
        float inv = 1.0f / fmaxf(cn, 1e-12f);
        cyx *= inv; cyy *= inv; cyz *= inv;
    }
    // cx = camy x n ; camx = -cx / ||cx||_1  (L1 normalize, matches reference)
    float cxx = cyy * nz - cyz * ny;
    float cxy = cyz * nx - cyx * nz;
    float cxz = cyx * ny - cyy * nx;
    {
        float l1   = fabsf(cxx) + fabsf(cxy) + fabsf(cxz);
        float invl = -1.0f / fmaxf(l1, 1e-12f);
        cxx *= invl; cxy *= invl; cxz *= invl;
    }

    const float invTwoPi = 0.5f / PI_F;
    const float dB0 = (diffuse[pix]            + 1.0f) * invTwoPi;
    const float dB1 = (diffuse[NPIX + pix]     + 1.0f) * invTwoPi;
    const float dB2 = (diffuse[2 * NPIX + pix] + 1.0f) * invTwoPi;

    const float rB  = (rough[pix] + 1.0f) * 0.5f;
    const float kk  = (rB + 1.0f) * (rB + 1.0f) * 0.125f;
    float a2 = rB * rB; a2 = a2 * a2;
    const float omk  = 1.0f - kk;
    const float ndv  = clamp01(nx * vx + ny * vy + nz * vz);
    const float nom1 = ndv * omk + kk;
    const float a2m1 = a2 - 1.0f;

    const float4* __restrict__ ex0p = g_env4[0];
    const float4* __restrict__ ex1p = g_env4[1];
    const float4* __restrict__ ey0p = g_env4[2];
    const float4* __restrict__ ey1p = g_env4[3];

    float aX00 = 0.f, aX01 = 0.f, aX02 = 0.f;
    float aX10 = 0.f, aX11 = 0.f, aX12 = 0.f;
    float aY00 = 0.f, aY01 = 0.f, aY02 = 0.f;
    float aY10 = 0.f, aY11 = 0.f, aY12 = 0.f;

    const int sbase = sub * 64;
    #pragma unroll 4
    for (int i = 0; i < 64; i++) {
        const int s  = sbase + i;
        const int iy = __ldg(idy + s * NPIX + pix);
        const int ix = __ldg(idx + s * NPIX + pix);
        const int p  = iy * EXW_ + ix;

        const float l0 = s_ls[3 * s + 0];
        const float l1 = s_ls[3 * s + 1];
        const float l2 = s_ls[3 * s + 2];

        // l = ls . basis
        const float lx = l0 * cxx + l1 * cyx + l2 * nx;
        const float ly = l0 * cxy + l1 * cyy + l2 * ny;
        const float lz = l0 * cxz + l1 * cyz + l2 * nz;

        // h = normalize((v + l)/2) with clip(dot, 1e-6)
        float hx = (vx + lx) * 0.5f;
        float hy = (vy + ly) * 0.5f;
        float hz = (vz + lz) * 0.5f;
        const float hd   = hx * hx + hy * hy + hz * hz;
        const float hinv = rsqrtf(fmaxf(hd, 1e-6f));
        hx *= hinv; hy *= hinv; hz *= hinv;

        const float vdh   = vx * hx + vy * hy + vz * hz;
        const float frac0 = 0.05f + 0.95f * exp2f((-5.55472f * vdh - 6.98316f) * vdh);

        const float ndh = clamp01(nx * hx + ny * hy + nz * hz);
        const float ndl = clamp01(nx * lx + ny * ly + nz * lz);

        const float nom0 = ndh * ndh * a2m1 + 1.0f;
        const float nom2 = ndl * omk + kk;
        float nom = 4.0f * PI_F * nom0 * nom0 * nom1 * nom2;
        nom = fminf(fmaxf(nom, 1e-6f), 4.0f * PI_F);
        const float spec = __fdividef(a2 * frac0, nom);

        const float w  = s_ew[s];
        const float t  = ndl * w;
        const float u  = 10.0f * spec * t;
        const float c0 = dB0 * t + u;
        const float c1 = dB1 * t + u;
        const float c2 = dB2 * t + u;

        const float4 ex0 = __ldg(ex0p + p);
        const float4 ex1 = __ldg(ex1p + p);
        const float4 ey0 = __ldg(ey0p + p);
        const float4 ey1 = __ldg(ey1p + p);

        aX00 += c0 * ex0.x; aX01 += c1 * ex0.y; aX02 += c2 * ex0.z;
        aX10 += c0 * ex1.x; aX11 += c1 * ex1.y; aX12 += c2 * ex1.z;
        aY00 += c0 * ey0.x; aY01 += c1 * ey0.y; aY02 += c2 * ey0.z;
        aY10 += c0 * ey1.x; aY11 += c1 * ey1.y; aY12 += c2 * ey1.z;
    }

    // combine the two sample-halves of each pixel (lanes differ in bit 0)
    #define CMB(v) v += __shfl_xor_sync(0xffffffffu, v, 1)
    CMB(aX00); CMB(aX01); CMB(aX02);
    CMB(aX10); CMB(aX11); CMB(aX12);
    CMB(aY00); CMB(aY01); CMB(aY02);
    CMB(aY10); CMB(aY11); CMB(aY12);
    #undef CMB

    float lp = 0.0f, sv = 0.0f;
    if (sub == 0) {
        // outputs: [0]=loss, [1 .. 1+3*NPIX) = pred[0], then gt[0]
        out[1 + 0 * NPIX + pix] = aX00;
        out[1 + 1 * NPIX + pix] = aX01;
        out[1 + 2 * NPIX + pix] = aX02;
        out[1 + 3 * NPIX + 0 * NPIX + pix] = aY00;
        out[1 + 3 * NPIX + 1 * NPIX + pix] = aY01;
        out[1 + 3 * NPIX + 2 * NPIX + pix] = aY02;

        float d;
        d = aX00 - aY00; lp += d * d;
        d = aX01 - aY01; lp += d * d;
        d = aX02 - aY02; lp += d * d;
        d = aX10 - aY10; lp += d * d;
        d = aX11 - aY11; lp += d * d;
        d = aX12 - aY12; lp += d * d;
        sv = seg[pix];
    }

    // block reduce (warp shuffles, then warp 0)
    #pragma unroll
    for (int o = 16; o > 0; o >>= 1) {
        lp += __shfl_xor_sync(0xffffffffu, lp, o);
        sv += __shfl_xor_sync(0xffffffffu, sv, o);
    }
    const int wid = tid >> 5;
    if ((tid & 31) == 0) { s_red[wid] = (double)lp; s_red[8 + wid] = (double)sv; }
    __syncthreads();
    if (tid == 0) {
        double bl = 0.0, bs = 0.0;
        #pragma unroll
        for (int w = 0; w < 8; w++) { bl += s_red[w]; bs += s_red[8 + w]; }
        g_pl[blockIdx.x] = bl;
        g_ps[blockIdx.x] = bs;
        __threadfence();
        unsigned int prev = atomicAdd(&g_done, 1u);
        s_red[0] = (prev == (unsigned int)(gridDim.x - 1)) ? 1.0 : 0.0;
    }
    __syncthreads();

    // last finished block performs the final reduction (warp 0, fixed order)
    if (s_red[0] != 0.0 && wid == 0) {
        double tl = 0.0, ts = 0.0;
        for (int b = tid; b < RBLOCKS; b += 32) { tl += g_pl[b]; ts += g_ps[b]; }
        #pragma unroll
        for (int o = 16; o > 0; o >>= 1) {
            tl += __shfl_xor_sync(0xffffffffu, tl, o);
            ts += __shfl_xor_sync(0xffffffffu, ts, o);
        }
        if (tid == 0) {
            out[0] = (float)(tl / (ts * 6.0));   // pixel_num = seg.sum()*B*3
            g_done = 0u;                         // reset for next graph replay
        }
    }
}

extern "C" void kernel_launch(void* const* d_in, const int* in_sizes, int n_in,
                              void* d_out, int out_size) {
    const float* x       = (const float*)d_in[0];
    const float* y       = (const float*)d_in[1];
    const float* diffuse = (const float*)d_in[2];
    const float* normal  = (const float*)d_in[3];
    const float* rough   = (const float*)d_in[4];
    const float* seg     = (const float*)d_in[5];
    const float* v       = (const float*)d_in[6];
    const float* ls      = (const float*)d_in[7];
    const float* ew      = (const float*)d_in[8];
    const int*   idy     = (const int*)d_in[9];
    const int*   idx     = (const int*)d_in[10];
    float* out = (float*)d_out;

    pack_kernel<<<(4 * NTEX) / 256, 256>>>(x, y);
    render_kernel<<<RBLOCKS, 256>>>(diffuse, normal, rough, seg, v,
                                    ls, ew, idy, idx, out);
}

// round 5
// speedup vs baseline: 1.3490x; 1.3490x over previous
#include <cuda_runtime.h>
#include <math.h>

#define NPIX  65536       // 256*256
#define SSAMP 128
#define EXW_  256
#define EXH_  128
#define NTEX  (EXH_*EXW_) // 32768 texels per batch image
#define PI_F  3.14159265358979f
#define RBLOCKS 512       // render grid (2 threads/pixel, 256 threads/block)

// Interleaved env records: per texel, 4 float4 = 64 bytes:
//   [0]=x batch0, [1]=x batch1, [2]=y batch0, [3]=y batch1  (rgb + pad)
// One sample's 4 gathers all land in the same 64B => same 128B L1 line.
__device__ float4 g_envP[NTEX][4];

// per-block partials + completion counter for fused reduction
__device__ double g_pl[RBLOCKS];
__device__ double g_ps[RBLOCKS];
__device__ unsigned int g_done;

__device__ __forceinline__ float clamp01(float x) {
    return fminf(fmaxf(x, 0.0f), 1.0f);
}

__global__ __launch_bounds__(256) void pack_kernel(
    const float* __restrict__ x, const float* __restrict__ y)
{
    int j   = blockIdx.x * 256 + threadIdx.x;   // 0..131071
    int arr = j & 3;                            // record slot
    int t   = j >> 2;                           // texel
    const float* src = (arr < 2 ? x : y) + ((size_t)(arr & 1) * NTEX + t) * 3;
    g_envP[t][arr] = make_float4(src[0], src[1], src[2], 0.0f);
}

__global__ __launch_bounds__(256, 4) void render_kernel(
    const float* __restrict__ diffuse,// (3,256,256)
    const float* __restrict__ normal, // (3,256,256)
    const float* __restrict__ rough,  // (1,256,256)
    const float* __restrict__ seg,    // (256,256)
    const float* __restrict__ vmap,   // (3,256,256)
    const float* __restrict__ ls,     // (1,128,3)
    const float* __restrict__ ew,     // (1,128,1)
    const int*   __restrict__ idy,    // (128,256,256)
    const int*   __restrict__ idx,    // (128,256,256)
    float* __restrict__ out)          // [1 + 2*3*65536]
{
    __shared__ float s_ls[SSAMP * 3];
    __shared__ float s_ew[SSAMP];
    __shared__ double s_red[16];

    const int tid = threadIdx.x;
    for (int i = tid; i < SSAMP * 3; i += 256) s_ls[i] = ls[i];
    for (int i = tid; i < SSAMP;     i += 256) s_ew[i] = ew[i];
    __syncthreads();

    const int gt  = blockIdx.x * 256 + tid;
    const int pix = gt >> 1;       // 2 threads per pixel
    const int sub = gt & 1;        // sample half

    // ---- per-pixel constants ----
    const float nx = normal[pix], ny = normal[NPIX + pix], nz = normal[2 * NPIX + pix];
    const float vx = vmap[pix],   vy = vmap[NPIX + pix],   vz = vmap[2 * NPIX + pix];

    // camy = normalize(up - (up.n) n), up = (0,1,0)
    float cyx = -ny * nx;
    float cyy = 1.0f - ny * ny;
    float cyz = -ny * nz;
    {
        float cn  = sqrtf(cyx * cyx + cyy * cyy + cyz * cyz);
        float inv = 1.0f / fmaxf(cn, 1e-12f);
        cyx *= inv; cyy *= inv; cyz *= inv;
    }
    // cx = camy x n ; camx = -cx / ||cx||_1  (L1 normalize, matches reference)
    float cxx = cyy * nz - cyz * ny;
    float cxy = cyz * nx - cyx * nz;
    float cxz = cyx * ny - cyy * nx;
    {
        float l1   = fabsf(cxx) + fabsf(cxy) + fabsf(cxz);
        float invl = -1.0f / fmaxf(l1, 1e-12f);
        cxx *= invl; cxy *= invl; cxz *= invl;
    }

    const float invTwoPi = 0.5f / PI_F;
    const float dB0 = (diffuse[pix]            + 1.0f) * invTwoPi;
    const float dB1 = (diffuse[NPIX + pix]     + 1.0f) * invTwoPi;
    const float dB2 = (diffuse[2 * NPIX + pix] + 1.0f) * invTwoPi;

    const float rB  = (rough[pix] + 1.0f) * 0.5f;
    const float kk  = (rB + 1.0f) * (rB + 1.0f) * 0.125f;
    float a2 = rB * rB; a2 = a2 * a2;
    const float omk  = 1.0f - kk;
    const float ndv  = clamp01(nx * vx + ny * vy + nz * vz);
    const float nom1 = ndv * omk + kk;
    const float a2m1 = a2 - 1.0f;

    const float4* __restrict__ envP = &g_envP[0][0];

    float aX00 = 0.f, aX01 = 0.f, aX02 = 0.f;
    float aX10 = 0.f, aX11 = 0.f, aX12 = 0.f;
    float aY00 = 0.f, aY01 = 0.f, aY02 = 0.f;
    float aY10 = 0.f, aY11 = 0.f, aY12 = 0.f;

    const int sbase = sub * 64;
    const int* idyp = idy + sbase * NPIX + pix;
    const int* idxp = idx + sbase * NPIX + pix;

    #pragma unroll 4
    for (int i = 0; i < 64; i++) {
        const int s  = sbase + i;
        const int iy = __ldg(idyp + i * NPIX);
        const int ix = __ldg(idxp + i * NPIX);
        const int p  = (iy * EXW_ + ix) * 4;   // record index in float4 units

        const float l0 = s_ls[3 * s + 0];
        const float l1 = s_ls[3 * s + 1];
        const float l2 = s_ls[3 * s + 2];

        // issue all 4 gathers early (same 128B line, loads 2-4 are L1 hits)
        const float4 ex0 = __ldg(envP + p + 0);
        const float4 ex1 = __ldg(envP + p + 1);
        const float4 ey0 = __ldg(envP + p + 2);
        const float4 ey1 = __ldg(envP + p + 3);

        // l = ls . basis
        const float lx = l0 * cxx + l1 * cyx + l2 * nx;
        const float ly = l0 * cxy + l1 * cyy + l2 * ny;
        const float lz = l0 * cxz + l1 * cyz + l2 * nz;

        // h = normalize((v + l)/2) with clip(dot, 1e-6)
        float hx = (vx + lx) * 0.5f;
        float hy = (vy + ly) * 0.5f;
        float hz = (vz + lz) * 0.5f;
        const float hd   = hx * hx + hy * hy + hz * hz;
        const float hinv = rsqrtf(fmaxf(hd, 1e-6f));
        hx *= hinv; hy *= hinv; hz *= hinv;

        const float vdh   = vx * hx + vy * hy + vz * hz;
        const float frac0 = 0.05f + 0.95f * exp2f((-5.55472f * vdh - 6.98316f) * vdh);

        const float ndh = clamp01(nx * hx + ny * hy + nz * hz);
        const float ndl = clamp01(nx * lx + ny * ly + nz * lz);

        const float nom0 = ndh * ndh * a2m1 + 1.0f;
        const float nom2 = ndl * omk + kk;
        float nom = 4.0f * PI_F * nom0 * nom0 * nom1 * nom2;
        nom = fminf(fmaxf(nom, 1e-6f), 4.0f * PI_F);
        const float spec = __fdividef(a2 * frac0, nom);

        const float w  = s_ew[s];
        const float t  = ndl * w;
        const float u  = 10.0f * spec * t;
        const float c0 = dB0 * t + u;
        const float c1 = dB1 * t + u;
        const float c2 = dB2 * t + u;

        aX00 += c0 * ex0.x; aX01 += c1 * ex0.y; aX02 += c2 * ex0.z;
        aX10 += c0 * ex1.x; aX11 += c1 * ex1.y; aX12 += c2 * ex1.z;
        aY00 += c0 * ey0.x; aY01 += c1 * ey0.y; aY02 += c2 * ey0.z;
        aY10 += c0 * ey1.x; aY11 += c1 * ey1.y; aY12 += c2 * ey1.z;
    }

    // combine the two sample-halves of each pixel (lanes differ in bit 0)
    #define CMB(v) v += __shfl_xor_sync(0xffffffffu, v, 1)
    CMB(aX00); CMB(aX01); CMB(aX02);
    CMB(aX10); CMB(aX11); CMB(aX12);
    CMB(aY00); CMB(aY01); CMB(aY02);
    CMB(aY10); CMB(aY11); CMB(aY12);
    #undef CMB

    float lp = 0.0f, sv = 0.0f;
    if (sub == 0) {
        // outputs: [0]=loss, [1 .. 1+3*NPIX) = pred[0], then gt[0]
        out[1 + 0 * NPIX + pix] = aX00;
        out[1 + 1 * NPIX + pix] = aX01;
        out[1 + 2 * NPIX + pix] = aX02;
        out[1 + 3 * NPIX + 0 * NPIX + pix] = aY00;
        out[1 + 3 * NPIX + 1 * NPIX + pix] = aY01;
        out[1 + 3 * NPIX + 2 * NPIX + pix] = aY02;

        float d;
        d = aX00 - aY00; lp += d * d;
        d = aX01 - aY01; lp += d * d;
        d = aX02 - aY02; lp += d * d;
        d = aX10 - aY10; lp += d * d;
        d = aX11 - aY11; lp += d * d;
        d = aX12 - aY12; lp += d * d;
        sv = seg[pix];
    }

    // block reduce (warp shuffles, then warp 0)
    #pragma unroll
    for (int o = 16; o > 0; o >>= 1) {
        lp += __shfl_xor_sync(0xffffffffu, lp, o);
        sv += __shfl_xor_sync(0xffffffffu, sv, o);
    }
    const int wid = tid >> 5;
    if ((tid & 31) == 0) { s_red[wid] = (double)lp; s_red[8 + wid] = (double)sv; }
    __syncthreads();
    if (tid == 0) {
        double bl = 0.0, bs = 0.0;
        #pragma unroll
        for (int w = 0; w < 8; w++) { bl += s_red[w]; bs += s_red[8 + w]; }
        g_pl[blockIdx.x] = bl;
        g_ps[blockIdx.x] = bs;
        __threadfence();
        unsigned int prev = atomicAdd(&g_done, 1u);
        s_red[0] = (prev == (unsigned int)(gridDim.x - 1)) ? 1.0 : 0.0;
    }
    __syncthreads();

    // last finished block performs the final reduction (warp 0, fixed order)
    if (s_red[0] != 0.0 && wid == 0) {
        double tl = 0.0, ts = 0.0;
        for (int b = tid; b < RBLOCKS; b += 32) { tl += g_pl[b]; ts += g_ps[b]; }
        #pragma unroll
        for (int o = 16; o > 0; o >>= 1) {
            tl += __shfl_xor_sync(0xffffffffu, tl, o);
            ts += __shfl_xor_sync(0xffffffffu, ts, o);
        }
        if (tid == 0) {
            out[0] = (float)(tl / (ts * 6.0));   // pixel_num = seg.sum()*B*3
            g_done = 0u;                         // reset for next graph replay
        }
    }
}

extern "C" void kernel_launch(void* const* d_in, const int* in_sizes, int n_in,
                              void* d_out, int out_size) {
    const float* x       = (const float*)d_in[0];
    const float* y       = (const float*)d_in[1];
    const float* diffuse = (const float*)d_in[2];
    const float* normal  = (const float*)d_in[3];
    const float* rough   = (const float*)d_in[4];
    const float* seg     = (const float*)d_in[5];
    const float* v       = (const float*)d_in[6];
    const float* ls      = (const float*)d_in[7];
    const float* ew      = (const float*)d_in[8];
    const int*   idy     = (const int*)d_in[9];
    const int*   idx     = (const int*)d_in[10];
    float* out = (float*)d_out;

    pack_kernel<<<(4 * NTEX) / 256, 256>>>(x, y);
    render_kernel<<<RBLOCKS, 256>>>(diffuse, normal, rough, seg, v,
                                    ls, ew, idy, idx, out);
}

// round 6
// speedup vs baseline: 2.5024x; 1.8550x over previous
#include <cuda_runtime.h>
#include <math.h>

#define NPIX  65536       // 256*256
#define SSAMP 128
#define EXW_  256
#define EXH_  128
#define NTEX  (EXH_*EXW_) // 32768 texels per batch image
#define PI_F  3.14159265358979f
#define RBLOCKS 1024      // render grid (4 threads/pixel, 256 threads/block)

// Interleaved env records: per texel, 4 float4 = 64 bytes:
//   [0]=x batch0, [1]=x batch1, [2]=y batch0, [3]=y batch1  (rgb + pad)
__device__ float4 g_envP[NTEX][4];

// per-block partials + completion counter for fused reduction
__device__ double g_pl[RBLOCKS];
__device__ double g_ps[RBLOCKS];
__device__ unsigned int g_done;

__device__ __forceinline__ float clamp01(float x) {
    return fminf(fmaxf(x, 0.0f), 1.0f);
}

__global__ __launch_bounds__(256) void pack_kernel(
    const float* __restrict__ x, const float* __restrict__ y)
{
    int j   = blockIdx.x * 256 + threadIdx.x;   // 0..131071
    int arr = j & 3;                            // record slot
    int t   = j >> 2;                           // texel
    const float* src = (arr < 2 ? x : y) + ((size_t)(arr & 1) * NTEX + t) * 3;
    g_envP[t][arr] = make_float4(src[0], src[1], src[2], 0.0f);
}

__global__ __launch_bounds__(256, 4) void render_kernel(
    const float* __restrict__ diffuse,// (3,256,256)
    const float* __restrict__ normal, // (3,256,256)
    const float* __restrict__ rough,  // (1,256,256)
    const float* __restrict__ seg,    // (256,256)
    const float* __restrict__ vmap,   // (3,256,256)
    const float* __restrict__ ls,     // (1,128,3)
    const float* __restrict__ ew,     // (1,128,1)
    const int*   __restrict__ idy,    // (128,256,256)
    const int*   __restrict__ idx,    // (128,256,256)
    float* __restrict__ out)          // [1 + 2*3*65536]
{
    __shared__ float s_ls[SSAMP * 3];
    __shared__ float s_ew[SSAMP];
    __shared__ double s_red[16];

    const int tid = threadIdx.x;
    for (int i = tid; i < SSAMP * 3; i += 256) s_ls[i] = ls[i];
    for (int i = tid; i < SSAMP;     i += 256) s_ew[i] = ew[i];
    __syncthreads();

    const int gt   = blockIdx.x * 256 + tid;
    const int pix  = gt >> 2;          // 4 threads per pixel
    const int slot = gt & 3;           // env record slot owned by this lane
    const int lane = tid & 31;
    const int gbase = lane & 28;       // first lane of this 4-lane group

    // ---- per-pixel constants (computed by all 4 lanes; broadcast loads) ----
    const float nx = normal[pix], ny = normal[NPIX + pix], nz = normal[2 * NPIX + pix];
    const float vx = vmap[pix],   vy = vmap[NPIX + pix],   vz = vmap[2 * NPIX + pix];

    // camy = normalize(up - (up.n) n), up = (0,1,0)
    float cyx = -ny * nx;
    float cyy = 1.0f - ny * ny;
    float cyz = -ny * nz;
    {
        float cn  = sqrtf(cyx * cyx + cyy * cyy + cyz * cyz);
        float inv = 1.0f / fmaxf(cn, 1e-12f);
        cyx *= inv; cyy *= inv; cyz *= inv;
    }
    // cx = camy x n ; camx = -cx / ||cx||_1  (L1 normalize, matches reference)
    float cxx = cyy * nz - cyz * ny;
    float cxy = cyz * nx - cyx * nz;
    float cxz = cyx * ny - cyy * nx;
    {
        float l1   = fabsf(cxx) + fabsf(cxy) + fabsf(cxz);
        float invl = -1.0f / fmaxf(l1, 1e-12f);
        cxx *= invl; cxy *= invl; cxz *= invl;
    }

    const float invTwoPi = 0.5f / PI_F;
    const float dB0 = (diffuse[pix]            + 1.0f) * invTwoPi;
    const float dB1 = (diffuse[NPIX + pix]     + 1.0f) * invTwoPi;
    const float dB2 = (diffuse[2 * NPIX + pix] + 1.0f) * invTwoPi;

    const float rB  = (rough[pix] + 1.0f) * 0.5f;
    const float kk  = (rB + 1.0f) * (rB + 1.0f) * 0.125f;
    float a2 = rB * rB; a2 = a2 * a2;
    const float omk  = 1.0f - kk;
    const float ndv  = clamp01(nx * vx + ny * vy + nz * vz);
    const float nom1 = ndv * omk + kk;
    const float a2m1 = a2 - 1.0f;

    const float4* __restrict__ envP = &g_envP[0][0];

    // per-lane accumulators for its slot: P = sum t*env, Q = sum u*env
    float P0 = 0.f, P1 = 0.f, P2 = 0.f;
    float Q0 = 0.f, Q1 = 0.f, Q2 = 0.f;

    // this lane computes math for samples s = 4*chunk + slot
    const int* idyp = idy + slot * NPIX + pix;
    const int* idxp = idx + slot * NPIX + pix;

    for (int chunk = 0; chunk < SSAMP / 4; chunk++) {
        const int s  = chunk * 4 + slot;
        const int iy = __ldg(idyp + chunk * 4 * NPIX);
        const int ix = __ldg(idxp + chunk * 4 * NPIX);
        const int p  = iy * EXW_ + ix;   // texel index

        const float l0 = s_ls[3 * s + 0];
        const float l1 = s_ls[3 * s + 1];
        const float l2 = s_ls[3 * s + 2];

        // l = ls . basis
        const float lx = l0 * cxx + l1 * cyx + l2 * nx;
        const float ly = l0 * cxy + l1 * cyy + l2 * ny;
        const float lz = l0 * cxz + l1 * cyz + l2 * nz;

        // h = normalize((v + l)/2) with clip(dot, 1e-6)
        float hx = (vx + lx) * 0.5f;
        float hy = (vy + ly) * 0.5f;
        float hz = (vz + lz) * 0.5f;
        const float hd   = hx * hx + hy * hy + hz * hz;
        const float hinv = rsqrtf(fmaxf(hd, 1e-6f));
        hx *= hinv; hy *= hinv; hz *= hinv;

        const float vdh   = vx * hx + vy * hy + vz * hz;
        const float frac0 = 0.05f + 0.95f * exp2f((-5.55472f * vdh - 6.98316f) * vdh);

        const float ndh = clamp01(nx * hx + ny * hy + nz * hz);
        const float ndl = clamp01(nx * lx + ny * ly + nz * lz);

        const float nom0 = ndh * ndh * a2m1 + 1.0f;
        const float nom2 = ndl * omk + kk;
        float nom = 4.0f * PI_F * nom0 * nom0 * nom1 * nom2;
        nom = fminf(fmaxf(nom, 1e-6f), 4.0f * PI_F);
        const float spec = __fdividef(a2 * frac0, nom);

        const float t = ndl * s_ew[s];   // diffuse weight
        const float u = spec * t;        // specular weight (x10 applied at end)

        // exchange (t,u,p) within the 4-lane group; all 4 lanes then gather
        // slot `slot` of the SAME texel in the SAME LDG -> shared 64B line.
        #pragma unroll
        for (int j = 0; j < 4; j++) {
            const float tj = __shfl_sync(0xffffffffu, t, gbase + j);
            const float uj = __shfl_sync(0xffffffffu, u, gbase + j);
            const int   pj = __shfl_sync(0xffffffffu, p, gbase + j);
            const float4 e = __ldg(envP + pj * 4 + slot);
            P0 += tj * e.x; P1 += tj * e.y; P2 += tj * e.z;
            Q0 += uj * e.x; Q1 += uj * e.y; Q2 += uj * e.z;
        }
    }

    // final per-slot color: res_c = dB_c * P_c + 10 * Q_c
    const float r0 = dB0 * P0 + 10.0f * Q0;
    const float r1 = dB1 * P1 + 10.0f * Q1;
    const float r2 = dB2 * P2 + 10.0f * Q2;

    // outputs: [0]=loss, [1..1+3*NPIX)=pred[0] (slot0), then gt[0] (slot2)
    if (slot == 0) {
        out[1 + 0 * NPIX + pix] = r0;
        out[1 + 1 * NPIX + pix] = r1;
        out[1 + 2 * NPIX + pix] = r2;
    } else if (slot == 2) {
        out[1 + 3 * NPIX + 0 * NPIX + pix] = r0;
        out[1 + 3 * NPIX + 1 * NPIX + pix] = r1;
        out[1 + 3 * NPIX + 2 * NPIX + pix] = r2;
    }

    // loss: X - Y pairs are (slot0,slot2) and (slot1,slot3) -> shfl_xor 2
    const float d0 = r0 - __shfl_xor_sync(0xffffffffu, r0, 2);
    const float d1 = r1 - __shfl_xor_sync(0xffffffffu, r1, 2);
    const float d2 = r2 - __shfl_xor_sync(0xffffffffu, r2, 2);

    float lp = 0.0f, sv = 0.0f;
    if (slot < 2) lp = d0 * d0 + d1 * d1 + d2 * d2;  // slots 2,3 would duplicate
    if (slot == 0) sv = seg[pix];

    // block reduce (warp shuffles, then warp 0)
    #pragma unroll
    for (int o = 16; o > 0; o >>= 1) {
        lp += __shfl_xor_sync(0xffffffffu, lp, o);
        sv += __shfl_xor_sync(0xffffffffu, sv, o);
    }
    const int wid = tid >> 5;
    if (lane == 0) { s_red[wid] = (double)lp; s_red[8 + wid] = (double)sv; }
    __syncthreads();
    if (tid == 0) {
        double bl = 0.0, bs = 0.0;
        #pragma unroll
        for (int w = 0; w < 8; w++) { bl += s_red[w]; bs += s_red[8 + w]; }
        g_pl[blockIdx.x] = bl;
        g_ps[blockIdx.x] = bs;
        __threadfence();
        unsigned int prev = atomicAdd(&g_done, 1u);
        s_red[0] = (prev == (unsigned int)(gridDim.x - 1)) ? 1.0 : 0.0;
    }
    __syncthreads();

    // last finished block performs the final reduction (warp 0, fixed order)
    if (s_red[0] != 0.0 && wid == 0) {
        double tl = 0.0, ts = 0.0;
        for (int b = lane; b < RBLOCKS; b += 32) { tl += g_pl[b]; ts += g_ps[b]; }
        #pragma unroll
        for (int o = 16; o > 0; o >>= 1) {
            tl += __shfl_xor_sync(0xffffffffu, tl, o);
            ts += __shfl_xor_sync(0xffffffffu, ts, o);
        }
        if (lane == 0) {
            out[0] = (float)(tl / (ts * 6.0));   // pixel_num = seg.sum()*B*3
            g_done = 0u;                         // reset for next graph replay
        }
    }
}

extern "C" void kernel_launch(void* const* d_in, const int* in_sizes, int n_in,
                              void* d_out, int out_size) {
    const float* x       = (const float*)d_in[0];
    const float* y       = (const float*)d_in[1];
    const float* diffuse = (const float*)d_in[2];
    const float* normal  = (const float*)d_in[3];
    const float* rough   = (const float*)d_in[4];
    const float* seg     = (const float*)d_in[5];
    const float* v       = (const float*)d_in[6];
    const float* ls      = (const float*)d_in[7];
    const float* ew      = (const float*)d_in[8];
    const int*   idy     = (const int*)d_in[9];
    const int*   idx     = (const int*)d_in[10];
    float* out = (float*)d_out;

    pack_kernel<<<(4 * NTEX) / 256, 256>>>(x, y);
    render_kernel<<<RBLOCKS, 256>>>(diffuse, normal, rough, seg, v,
                                    ls, ew, idy, idx, out);
}

// round 8
// speedup vs baseline: 2.6148x; 1.0449x over previous
#include <cuda_runtime.h>
#include <math.h>

#define NPIX  65536       // 256*256
#define SSAMP 128
#define EXW_  256
#define EXH_  128
#define NTEX  (EXH_*EXW_) // 32768 texels per batch image
#define PI_F  3.14159265358979f
#define RBLOCKS 1024      // render grid (4 threads/pixel, 256 threads/block)

// Interleaved env records: per texel, 4 float4 = 64 bytes:
//   [0]=x batch0, [1]=x batch1, [2]=y batch0, [3]=y batch1  (rgb + pad)
__device__ float4 g_envP[NTEX][4];

// per-block partials + completion counter for fused reduction
__device__ double g_pl[RBLOCKS];
__device__ double g_ps[RBLOCKS];
__device__ unsigned int g_done;

__device__ __forceinline__ float clamp01(float x) {
    return fminf(fmaxf(x, 0.0f), 1.0f);
}

__global__ __launch_bounds__(256) void pack_kernel(
    const float* __restrict__ x, const float* __restrict__ y)
{
    int j   = blockIdx.x * 256 + threadIdx.x;   // 0..131071
    int arr = j & 3;                            // record slot
    int t   = j >> 2;                           // texel
    const float* src = (arr < 2 ? x : y) + ((size_t)(arr & 1) * NTEX + t) * 3;
    g_envP[t][arr] = make_float4(src[0], src[1], src[2], 0.0f);
}

__global__ __launch_bounds__(256, 4) void render_kernel(
    const float* __restrict__ diffuse,// (3,256,256)
    const float* __restrict__ normal, // (3,256,256)
    const float* __restrict__ rough,  // (1,256,256)
    const float* __restrict__ seg,    // (256,256)
    const float* __restrict__ vmap,   // (3,256,256)
    const float* __restrict__ ls,     // (1,128,3)
    const float* __restrict__ ew,     // (1,128,1)
    const int*   __restrict__ idy,    // (128,256,256)
    const int*   __restrict__ idx,    // (128,256,256)
    float* __restrict__ out)          // [1 + 2*3*65536]
{
    // per-sample constants:
    //   s_samp[s] = (l0, l1, l2, t = l2*ew[s])   [ndl == l2 since camx,camy ⊥ n]
    //   s_ab[s]   = (a = l0^2, b = l1^2 + l2^2)
    //   s_t4[ch]  = (t of samples 4ch..4ch+3) for the gather-accumulate loop
    __shared__ float4 s_samp[SSAMP];
    __shared__ float2 s_ab[SSAMP];
    __shared__ float4 s_t4[SSAMP / 4];
    __shared__ double s_red[16];

    const int tid = threadIdx.x;
    if (tid < SSAMP) {
        const float l0 = ls[3 * tid + 0];
        const float l1 = ls[3 * tid + 1];
        const float l2 = ls[3 * tid + 2];
        const float t  = l2 * ew[tid];           // clamp01(l2) == l2 (cos El > 0)
        s_samp[tid] = make_float4(l0, l1, l2, t);
        s_ab[tid]   = make_float2(l0 * l0, l1 * l1 + l2 * l2);
        ((float*)s_t4)[tid] = 0.0f;              // placeholder, overwritten below
    }
    __syncthreads();
    if (tid < SSAMP) ((float*)s_t4)[tid] = s_samp[tid].w;  // t4[ch] = (t0,t1,t2,t3)
    __syncthreads();

    const int gt   = blockIdx.x * 256 + tid;
    const int pix  = gt >> 2;          // 4 threads per pixel
    const int slot = gt & 3;           // env record slot owned by this lane
    const int lane = tid & 31;
    const int gbase = lane & 28;       // first lane of this 4-lane group

    // ---- per-pixel constants ----
    const float nx = normal[pix], ny = normal[NPIX + pix], nz = normal[2 * NPIX + pix];
    const float vx = vmap[pix],   vy = vmap[NPIX + pix],   vz = vmap[2 * NPIX + pix];

    // camy = normalize(up - (up.n) n), up = (0,1,0)
    float cyx = -ny * nx;
    float cyy = 1.0f - ny * ny;
    float cyz = -ny * nz;
    {
        float cn  = sqrtf(cyx * cyx + cyy * cyy + cyz * cyz);
        float inv = 1.0f / fmaxf(cn, 1e-12f);
        cyx *= inv; cyy *= inv; cyz *= inv;
    }
    // cx = camy x n ; camx = -cx / ||cx||_1  (L1 normalize, matches reference)
    float cxx = cyy * nz - cyz * ny;
    float cxy = cyz * nx - cyx * nz;
    float cxz = cyx * ny - cyy * nx;
    {
        float l1n  = fabsf(cxx) + fabsf(cxy) + fabsf(cxz);
        float invl = -1.0f / fmaxf(l1n, 1e-12f);
        cxx *= invl; cxy *= invl; cxz *= invl;
    }

    // reduced per-pixel scalars (basis vectors die here)
    const float spix = cxx * cxx + cxy * cxy + cxz * cxz;  // |camx|^2
    const float vcx  = vx * cxx + vy * cxy + vz * cxz;     // v . camx
    const float vcy  = vx * cyx + vy * cyy + vz * cyz;     // v . camy
    const float nv   = nx * vx + ny * vy + nz * vz;        // n . v (raw)

    const float invTwoPi = 0.5f / PI_F;
    const float dB0 = (diffuse[pix]            + 1.0f) * invTwoPi;
    const float dB1 = (diffuse[NPIX + pix]     + 1.0f) * invTwoPi;
    const float dB2 = (diffuse[2 * NPIX + pix] + 1.0f) * invTwoPi;

    const float rB  = (rough[pix] + 1.0f) * 0.5f;
    const float kk  = (rB + 1.0f) * (rB + 1.0f) * 0.125f;
    float a2 = rB * rB; a2 = a2 * a2;
    const float omk  = 1.0f - kk;
    const float nom1 = clamp01(nv) * omk + kk;
    const float a2m1 = a2 - 1.0f;
    const float specK = a2;                       // numerator factor

    const float4* __restrict__ envP = &g_envP[0][0];

    float P0 = 0.f, P1 = 0.f, P2 = 0.f;   // sum t * env
    float Q0 = 0.f, Q1 = 0.f, Q2 = 0.f;   // sum (spec*t) * env

    const int* idyp = idy + slot * NPIX + pix;
    const int* idxp = idx + slot * NPIX + pix;

    for (int chunk = 0; chunk < SSAMP / 4; chunk++) {
        const int s  = chunk * 4 + slot;
        const int iy = __ldg(idyp + chunk * 4 * NPIX);
        const int ix = __ldg(idxp + chunk * 4 * NPIX);
        const int p  = iy * EXW_ + ix;   // texel index

        const float4 q  = s_samp[s];     // (l0, l1, l2, t)
        const float2 ab = s_ab[s];       // (l0^2, l1^2+l2^2)

        // c = v.l ; ll = |l|^2 ; hh = |(v+l)/2|^2
        const float c  = q.x * vcx + q.y * vcy + q.z * nv;
        const float ll = fmaf(ab.x, spix, ab.y);
        const float hh = fmaf(0.5f, c, fmaf(0.25f, ll, 0.25f));
        const float hv = 0.5f * rsqrtf(fmaxf(hh, 1e-6f));

        const float vdh   = (1.0f + c) * hv;
        const float frac0 = 0.05f + 0.95f * exp2f((-5.55472f * vdh - 6.98316f) * vdh);
        const float ndh   = clamp01((nv + q.z) * hv);

        const float nom0 = fmaf(ndh * ndh, a2m1, 1.0f);
        const float nom2 = fmaf(q.z, omk, kk);
        float nom = 4.0f * PI_F * nom0 * nom0 * nom1 * nom2;
        nom = fminf(fmaxf(nom, 1e-6f), 4.0f * PI_F);
        const float u = __fdividef(specK * frac0, nom) * q.w;  // spec * t

        const float4 t4 = s_t4[chunk];   // t of the 4 samples in this chunk
        const float tarr[4] = {t4.x, t4.y, t4.z, t4.w};

        // exchange (u, p) within the 4-lane group; each lane gathers its slot
        // of the SAME texel in the SAME LDG -> 4 lanes share one 64B record.
        #pragma unroll
        for (int j = 0; j < 4; j++) {
            const float uj = __shfl_sync(0xffffffffu, u, gbase + j);
            const int   pj = __shfl_sync(0xffffffffu, p, gbase + j);
            const float4 e = __ldg(envP + pj * 4 + slot);
            const float tj = tarr[j];
            P0 += tj * e.x; P1 += tj * e.y; P2 += tj * e.z;
            Q0 += uj * e.x; Q1 += uj * e.y; Q2 += uj * e.z;
        }
    }

    // final per-slot color: res_c = dB_c * P_c + 10 * Q_c
    const float r0 = dB0 * P0 + 10.0f * Q0;
    const float r1 = dB1 * P1 + 10.0f * Q1;
    const float r2 = dB2 * P2 + 10.0f * Q2;

    // outputs: [0]=loss, [1..1+3*NPIX)=pred[0] (slot0), then gt[0] (slot2)
    if (slot == 0) {
        out[1 + 0 * NPIX + pix] = r0;
        out[1 + 1 * NPIX + pix] = r1;
        out[1 + 2 * NPIX + pix] = r2;
    } else if (slot == 2) {
        out[1 + 3 * NPIX + 0 * NPIX + pix] = r0;
        out[1 + 3 * NPIX + 1 * NPIX + pix] = r1;
        out[1 + 3 * NPIX + 2 * NPIX + pix] = r2;
    }

    // loss: X - Y pairs are (slot0,slot2) and (slot1,slot3) -> shfl_xor 2
    const float d0 = r0 - __shfl_xor_sync(0xffffffffu, r0, 2);
    const float d1 = r1 - __shfl_xor_sync(0xffffffffu, r1, 2);
    const float d2 = r2 - __shfl_xor_sync(0xffffffffu, r2, 2);

    float lp = 0.0f, sv = 0.0f;
    if (slot < 2) lp = d0 * d0 + d1 * d1 + d2 * d2;  // slots 2,3 would duplicate
    if (slot == 0) sv = seg[pix];

    // block reduce (warp shuffles, then warp 0)
    #pragma unroll
    for (int o = 16; o > 0; o >>= 1) {
        lp += __shfl_xor_sync(0xffffffffu, lp, o);
        sv += __shfl_xor_sync(0xffffffffu, sv, o);
    }
    const int wid = tid >> 5;
    if (lane == 0) { s_red[wid] = (double)lp; s_red[8 + wid] = (double)sv; }
    __syncthreads();
    if (tid == 0) {
        double bl = 0.0, bs = 0.0;
        #pragma unroll
        for (int w = 0; w < 8; w++) { bl += s_red[w]; bs += s_red[8 + w]; }
        g_pl[blockIdx.x] = bl;
        g_ps[blockIdx.x] = bs;
        __threadfence();
        unsigned int prev = atomicAdd(&g_done, 1u);
        s_red[0] = (prev == (unsigned int)(gridDim.x - 1)) ? 1.0 : 0.0;
    }
    __syncthreads();

    // last finished block performs the final reduction (warp 0, fixed order)
    if (s_red[0] != 0.0 && wid == 0) {
        double tl = 0.0, ts = 0.0;
        for (int b = lane; b < RBLOCKS; b += 32) { tl += g_pl[b]; ts += g_ps[b]; }
        #pragma unroll
        for (int o = 16; o > 0; o >>= 1) {
            tl += __shfl_xor_sync(0xffffffffu, tl, o);
            ts += __shfl_xor_sync(0xffffffffu, ts, o);
        }
        if (lane == 0) {
            out[0] = (float)(tl / (ts * 6.0));   // pixel_num = seg.sum()*B*3
            g_done = 0u;                         // reset for next graph replay
        }
    }
}

extern "C" void kernel_launch(void* const* d_in, const int* in_sizes, int n_in,
                              void* d_out, int out_size) {
    const float* x       = (const float*)d_in[0];
    const float* y       = (const float*)d_in[1];
    const float* diffuse = (const float*)d_in[2];
    const float* normal  = (const float*)d_in[3];
    const float* rough   = (const float*)d_in[4];
    const float* seg     = (const float*)d_in[5];
    const float* v       = (const float*)d_in[6];
    const float* ls      = (const float*)d_in[7];
    const float* ew      = (const float*)d_in[8];
    const int*   idy     = (const int*)d_in[9];
    const int*   idx     = (const int*)d_in[10];
    float* out = (float*)d_out;

    pack_kernel<<<(4 * NTEX) / 256, 256>>>(x, y);
    render_kernel<<<RBLOCKS, 256>>>(diffuse, normal, rough, seg, v,
                                    ls, ew, idy, idx, out);
}